// round 12
// baseline (speedup 1.0000x reference)
#include <cuda_runtime.h>
#include <cuda_fp16.h>
#include <cstddef>
#include <cstdint>

// Problem constants (from reference):
//   pix_to_face : [N,H,W,K]      int32,  K = 4   (16B per pixel)
//   bary_coords : [N,H,W,K,3]    float32         (48B per pixel)
//   faces       : [F,3]          int32,  F = 200000
//   verts_colors: [V,3]          float32, V = 100000
//   output      : [N,H,W,3]      float32  (sample K=0 only)

#define KSAMP 4
#define F_MAX 200000
#define TILE  512                 // pixels per block
#define BLK   128                 // threads per block
#define PPT   (TILE / BLK)        // 4 pixels per thread
#define PIX_TILE_BYTES  (TILE * 16)   // 8192
#define BARY_TILE_BYTES (TILE * 48)   // 24576
#define TILE_TX_BYTES   (PIX_TILE_BYTES + BARY_TILE_BYTES) // 32768

__device__ __forceinline__ uint32_t h2_as_u32(__half2 h) {
    return *reinterpret_cast<uint32_t*>(&h);
}
__device__ __forceinline__ __half2 u32_as_h2(uint32_t u) {
    return *reinterpret_cast<__half2*>(&u);
}

// 32B per-face record: slot k (8B): u[2k]=(ck.x,ck.y), u[2k+1]=(ck.z,pad). 6.4MB, L2-resident.
struct alignas(32) FaceRec { uint32_t u[8]; };
__device__ FaceRec g_face_tab[F_MAX];

// 256-bit gather (compiles to paired LDG.128 if .256 unsupported; same sectors).
__device__ __forceinline__ void ldg256(const void* p, uint32_t* a) {
    asm volatile("ld.global.v8.b32 {%0,%1,%2,%3,%4,%5,%6,%7}, [%8];"
                 : "=r"(a[0]), "=r"(a[1]), "=r"(a[2]), "=r"(a[3]),
                   "=r"(a[4]), "=r"(a[5]), "=r"(a[6]), "=r"(a[7]) : "l"(p));
}

__device__ __forceinline__ uint32_t smem_u32(const void* p) {
    uint32_t a;
    asm("{ .reg .u64 t; cvta.to.shared.u64 t, %1; cvt.u32.u64 %0, t; }"
        : "=r"(a) : "l"(p));
    return a;
}

// ---------------------------------------------------------------------------
// Prepro: one thread per FACE-VERTEX (F*3). 1 coalesced idx load + 3 scalar
// vertex-color gathers + fp16 pack + one 8B store.  (R10-proven)
// ---------------------------------------------------------------------------
__global__ void __launch_bounds__(256)
build_face_tab(const int*   __restrict__ faces,
               const float* __restrict__ verts,
               int nfv)
{
    const int i = blockIdx.x * blockDim.x + threadIdx.x;
    if (i >= nfv) return;
    const int v = __ldg(faces + i);
    const float cx = __ldg(verts + (size_t)v * 3 + 0);
    const float cy = __ldg(verts + (size_t)v * 3 + 1);
    const float cz = __ldg(verts + (size_t)v * 3 + 2);
    uint2 h;
    h.x = h2_as_u32(__floats2half2_rn(cx, cy));
    h.y = h2_as_u32(__floats2half2_rn(cz, 0.0f));
    const int face = i / 3;
    const int slot = i - face * 3;
    reinterpret_cast<uint2*>(&g_face_tab[face])[slot] = h;
}

// ---------------------------------------------------------------------------
// Main: TMA-staged streaming. Per block: bulk-copy pix+bary tiles to SMEM via
// cp.async.bulk + mbarrier, then warps do LDS -> one gather level -> compute.
// ---------------------------------------------------------------------------
__global__ void __launch_bounds__(BLK)
unlit_shader_tma(const int*   __restrict__ pix_to_face,
                 const float* __restrict__ bary,
                 float*       __restrict__ out,
                 int npix)
{
    __shared__ __align__(128) uint8_t  s_pix[PIX_TILE_BYTES];
    __shared__ __align__(128) uint8_t  s_bary[BARY_TILE_BYTES];
    __shared__ __align__(8)   uint64_t s_mbar;

    const int t    = threadIdx.x;
    const int base = blockIdx.x * TILE;

    if (base + TILE <= npix) {
        // ---- TMA fill ----
        const uint32_t mbar = smem_u32(&s_mbar);
        if (t == 0) {
            asm volatile("mbarrier.init.shared.b64 [%0], %1;"
                         :: "r"(mbar), "r"(1) : "memory");
        }
        __syncthreads();
        if (t == 0) {
            asm volatile("mbarrier.arrive.expect_tx.shared.b64 _, [%0], %1;"
                         :: "r"(mbar), "r"((uint32_t)TILE_TX_BYTES) : "memory");
            asm volatile("cp.async.bulk.shared::cluster.global.mbarrier::complete_tx::bytes "
                         "[%0], [%1], %2, [%3];"
                         :: "r"(smem_u32(s_pix)),
                            "l"(reinterpret_cast<const uint8_t*>(pix_to_face) + (size_t)base * 16),
                            "r"((uint32_t)PIX_TILE_BYTES), "r"(mbar) : "memory");
            asm volatile("cp.async.bulk.shared::cluster.global.mbarrier::complete_tx::bytes "
                         "[%0], [%1], %2, [%3];"
                         :: "r"(smem_u32(s_bary)),
                            "l"(reinterpret_cast<const uint8_t*>(bary) + (size_t)base * 48),
                            "r"((uint32_t)BARY_TILE_BYTES), "r"(mbar) : "memory");
        }
        // Wait (parity 0), acquire semantics.
        {
            uint32_t done;
            asm volatile(
                "{\n\t.reg .pred p;\n\t"
                "mbarrier.try_wait.parity.acquire.cta.shared::cta.b64 p, [%1], 0;\n\t"
                "selp.b32 %0, 1, 0, p;\n\t}"
                : "=r"(done) : "r"(mbar) : "memory");
            if (!done) {
                asm volatile(
                    "{\n\t.reg .pred P1;\n\t"
                    "WL_%=:\n\t"
                    "mbarrier.try_wait.parity.acquire.cta.shared::cta.b64 P1, [%0], 0, 0x989680;\n\t"
                    "@P1 bra.uni WD_%=;\n\t"
                    "bra.uni WL_%=;\n\t"
                    "WD_%=:\n\t}"
                    :: "r"(mbar) : "memory");
            }
        }

        // ---- process 4 pixels: tile-local indices t, t+128, t+256, t+384 ----
        int   f[PPT];
        float w0[PPT], w1[PPT], w2[PPT];
#pragma unroll
        for (int j = 0; j < PPT; ++j) {
            const int tp = t + j * BLK;
            f[j]  = *reinterpret_cast<const int*>(s_pix + (size_t)tp * 16);
            const float* bw = reinterpret_cast<const float*>(s_bary + (size_t)tp * 48);
            w0[j] = bw[0]; w1[j] = bw[1]; w2[j] = bw[2];
        }

        // one gather per pixel, all independent
        uint32_t g[PPT][8];
#pragma unroll
        for (int j = 0; j < PPT; ++j) {
            const int fi = (f[j] >= 0) ? f[j] : 0;
            ldg256(&g_face_tab[fi], g[j]);
        }

#pragma unroll
        for (int j = 0; j < PPT; ++j) {
            float wx = w0[j], wy = w1[j], wz = w2[j];
            if (f[j] < 0) { wx = 0.f; wy = 0.f; wz = 0.f; }
            const float2 a0 = __half22float2(u32_as_h2(g[j][0]));
            const float2 a1 = __half22float2(u32_as_h2(g[j][1]));
            const float2 b0 = __half22float2(u32_as_h2(g[j][2]));
            const float2 b1 = __half22float2(u32_as_h2(g[j][3]));
            const float2 c0 = __half22float2(u32_as_h2(g[j][4]));
            const float2 c1 = __half22float2(u32_as_h2(g[j][5]));
            const int p = base + t + j * BLK;
            float* op = out + (size_t)p * 3;
            __stcs(op + 0, wx * a0.x + wy * b0.x + wz * c0.x);
            __stcs(op + 1, wx * a0.y + wy * b0.y + wz * c0.y);
            __stcs(op + 2, wx * a1.x + wy * b1.x + wz * c1.x);
        }
    } else {
        // ---- tail: direct-load fallback (no TMA) ----
        for (int j = 0; j < PPT; ++j) {
            const int p = base + t + j * BLK;
            if (p >= npix) continue;
            const int fv = __ldg(pix_to_face + (size_t)p * KSAMP);
            float rx = 0.f, ry = 0.f, rz = 0.f;
            if (fv >= 0) {
                const float wx = __ldg(bary + (size_t)p * (KSAMP * 3) + 0);
                const float wy = __ldg(bary + (size_t)p * (KSAMP * 3) + 1);
                const float wz = __ldg(bary + (size_t)p * (KSAMP * 3) + 2);
                uint32_t g[8];
                ldg256(&g_face_tab[fv], g);
                const float2 a0 = __half22float2(u32_as_h2(g[0]));
                const float2 a1 = __half22float2(u32_as_h2(g[1]));
                const float2 b0 = __half22float2(u32_as_h2(g[2]));
                const float2 b1 = __half22float2(u32_as_h2(g[3]));
                const float2 c0 = __half22float2(u32_as_h2(g[4]));
                const float2 c1 = __half22float2(u32_as_h2(g[5]));
                rx = wx * a0.x + wy * b0.x + wz * c0.x;
                ry = wx * a0.y + wy * b0.y + wz * c0.y;
                rz = wx * a1.x + wy * b1.x + wz * c1.x;
            }
            out[(size_t)p * 3 + 0] = rx;
            out[(size_t)p * 3 + 1] = ry;
            out[(size_t)p * 3 + 2] = rz;
        }
    }
}

extern "C" void kernel_launch(void* const* d_in, const int* in_sizes, int n_in,
                              void* d_out, int out_size)
{
    const int*   pix_to_face = (const int*)  d_in[0];
    const float* bary        = (const float*)d_in[1];
    const int*   faces       = (const int*)  d_in[2];
    const float* verts       = (const float*)d_in[3];
    float*       out         = (float*)      d_out;

    int nfv = in_sizes[2];                       // F*3 face-vertices
    if (nfv > F_MAX * 3) nfv = F_MAX * 3;
    const int npix = in_sizes[0] / KSAMP;        // N*H*W

    build_face_tab<<<(nfv + 255) / 256, 256>>>(faces, verts, nfv);

    const int grid = (npix + TILE - 1) / TILE;
    unlit_shader_tma<<<grid, BLK>>>(pix_to_face, bary, out, npix);
}

// round 14
// speedup vs baseline: 1.2526x; 1.2526x over previous
#include <cuda_runtime.h>
#include <cuda_fp16.h>
#include <cstddef>
#include <cstdint>

// Problem constants (from reference):
//   pix_to_face : [N,H,W,K]      int32,  K = 4
//   bary_coords : [N,H,W,K,3]    float32
//   faces       : [F,3]          int32,  F = 200000
//   verts_colors: [V,3]          float32, V = 100000
//   output      : [N,H,W,3]      float32  (sample K=0 only)

#define KSAMP 4
#define PPT 4
#define F_MAX 200000
#define BLOCK 256
#define WAVE_BLOCKS 1036           // 148 SMs x 7 resident blocks (regs ~38)

__device__ __forceinline__ uint32_t h2_as_u32(__half2 h) {
    return *reinterpret_cast<uint32_t*>(&h);
}
__device__ __forceinline__ __half2 u32_as_h2(uint32_t u) {
    return *reinterpret_cast<__half2*>(&u);
}

// 32B per-face record: slot k (8B): u[2k]=(ck.x,ck.y), u[2k+1]=(ck.z,pad). 6.4MB, L2-resident.
struct alignas(32) FaceRec { uint32_t u[8]; };
__device__ FaceRec g_face_tab[F_MAX];

// 256-bit global load (sm_103a); addr must be 32B-aligned.
__device__ __forceinline__ void ldg256(const void* p, uint32_t* a) {
    asm volatile("ld.global.v8.b32 {%0,%1,%2,%3,%4,%5,%6,%7}, [%8];"
                 : "=r"(a[0]), "=r"(a[1]), "=r"(a[2]), "=r"(a[3]),
                   "=r"(a[4]), "=r"(a[5]), "=r"(a[6]), "=r"(a[7]) : "l"(p));
}

// ---------------------------------------------------------------------------
// Prepro (R10-proven): one thread per FACE-VERTEX (F*3). 1 coalesced idx load
// + 3 scalar vertex gathers + fp16 pack + one 8B store at the PADDED slot
// address face*32 + slot*8.
// ---------------------------------------------------------------------------
__global__ void __launch_bounds__(BLOCK)
build_face_tab(const int*   __restrict__ faces,
               const float* __restrict__ verts,
               int nfv)
{
    const int i = blockIdx.x * blockDim.x + threadIdx.x;
    if (i >= nfv) return;
    const int v = __ldg(faces + i);
    const float cx = __ldg(verts + (size_t)v * 3 + 0);
    const float cy = __ldg(verts + (size_t)v * 3 + 1);
    const float cz = __ldg(verts + (size_t)v * 3 + 2);
    uint2 h;
    h.x = h2_as_u32(__floats2half2_rn(cx, cy));
    h.y = h2_as_u32(__floats2half2_rn(cz, 0.0f));
    const int face = i / 3;
    const int slot = i - face * 3;
    reinterpret_cast<uint2*>(&g_face_tab[face])[slot] = h;   // padded layout
}

// ---------------------------------------------------------------------------
// Main shader: R10-proven body in a one-wave grid-stride (2 iterations/thread).
// ---------------------------------------------------------------------------
__global__ void __launch_bounds__(BLOCK)
unlit_shader_kernel(const int*   __restrict__ pix_to_face,
                    const float* __restrict__ bary,
                    float*       __restrict__ out,
                    int npix)
{
    const int T   = (int)(gridDim.x * blockDim.x);
    const int tid = (int)(blockIdx.x * blockDim.x + threadIdx.x);
    const int ngroups = (npix + PPT - 1) / PPT;

    for (int grp = tid; grp < ngroups; grp += T) {
        const int p0 = grp * PPT;
        const bool full = (p0 + PPT <= npix);

        // 1) Face indices (vectorized int4, coalesced; sample K=0 in .x).
        int f[PPT];
#pragma unroll
        for (int j = 0; j < PPT; ++j) {
            const int p = p0 + j;
            if (full || p < npix) {
                const int4 s = __ldcs(reinterpret_cast<const int4*>(pix_to_face) + p);
                f[j] = s.x;
            } else {
                f[j] = -1;
            }
        }

        // 2) Barycentric weights (conditional: skips ~20% background traffic).
        float4 w[PPT];
#pragma unroll
        for (int j = 0; j < PPT; ++j) {
            const int p = p0 + j;
            w[j] = (f[j] >= 0)
                 ? __ldcs(reinterpret_cast<const float4*>(bary + (size_t)p * (KSAMP * 3)))
                 : make_float4(0.f, 0.f, 0.f, 0.f);
        }

        // 3) One 256-bit gather per pixel from the L2-resident fp16 table.
        uint32_t g[PPT][8];
#pragma unroll
        for (int j = 0; j < PPT; ++j) {
            const int fi = (f[j] >= 0) ? f[j] : 0;
            ldg256(&g_face_tab[fi], g[j]);
        }

        // 4) Unpack fp16 -> fp32, barycentric weighted sum.
        //    slot k: g[2k]=(ck.x,ck.y), g[2k+1]=(ck.z,pad)
        float o[PPT * 3];
#pragma unroll
        for (int j = 0; j < PPT; ++j) {
            const float2 a0 = __half22float2(u32_as_h2(g[j][0]));
            const float2 a1 = __half22float2(u32_as_h2(g[j][1]));
            const float2 b0 = __half22float2(u32_as_h2(g[j][2]));
            const float2 b1 = __half22float2(u32_as_h2(g[j][3]));
            const float2 c0 = __half22float2(u32_as_h2(g[j][4]));
            const float2 c1 = __half22float2(u32_as_h2(g[j][5]));
            const float wx = w[j].x, wy = w[j].y, wz = w[j].z;
            o[j * 3 + 0] = wx * a0.x + wy * b0.x + wz * c0.x;
            o[j * 3 + 1] = wx * a0.y + wy * b0.y + wz * c0.y;
            o[j * 3 + 2] = wx * a1.x + wy * b1.x + wz * c1.x;
        }

        // 5) Store 12 contiguous floats -> 3x STG.128, streaming.
        float* ob = out + (size_t)p0 * 3;
        if (full) {
            float4* o4 = reinterpret_cast<float4*>(ob);
            __stcs(o4 + 0, make_float4(o[0], o[1],  o[2],  o[3]));
            __stcs(o4 + 1, make_float4(o[4], o[5],  o[6],  o[7]));
            __stcs(o4 + 2, make_float4(o[8], o[9],  o[10], o[11]));
        } else {
#pragma unroll
            for (int j = 0; j < PPT; ++j) {
                const int p = p0 + j;
                if (p < npix) {
                    ob[j * 3 + 0] = o[j * 3 + 0];
                    ob[j * 3 + 1] = o[j * 3 + 1];
                    ob[j * 3 + 2] = o[j * 3 + 2];
                }
            }
        }
    }
}

extern "C" void kernel_launch(void* const* d_in, const int* in_sizes, int n_in,
                              void* d_out, int out_size)
{
    const int*   pix_to_face = (const int*)  d_in[0];
    const float* bary        = (const float*)d_in[1];
    const int*   faces       = (const int*)  d_in[2];
    const float* verts       = (const float*)d_in[3];
    float*       out         = (float*)      d_out;

    int nfv = in_sizes[2];                       // F*3 face-vertices
    if (nfv > F_MAX * 3) nfv = F_MAX * 3;
    const int npix = in_sizes[0] / KSAMP;        // N*H*W

    build_face_tab<<<(nfv + BLOCK - 1) / BLOCK, BLOCK>>>(faces, verts, nfv);

    const int ngroups = (npix + PPT - 1) / PPT;
    int grid = WAVE_BLOCKS;                      // one resident wave
    const int max_grid = (ngroups + BLOCK - 1) / BLOCK;
    if (grid > max_grid) grid = max_grid;
    if (grid < 1) grid = 1;
    unlit_shader_kernel<<<grid, BLOCK>>>(pix_to_face, bary, out, npix);
}

// round 15
// speedup vs baseline: 1.2795x; 1.0214x over previous
#include <cuda_runtime.h>
#include <cuda_fp16.h>
#include <cstddef>
#include <cstdint>

// Problem constants (from reference):
//   pix_to_face : [N,H,W,K]      int32,  K = 4
//   bary_coords : [N,H,W,K,3]    float32
//   faces       : [F,3]          int32,  F = 200000
//   verts_colors: [V,3]          float32, V = 100000
//   output      : [N,H,W,3]      float32  (sample K=0 only)

#define KSAMP 4
#define PPT 4
#define F_MAX 200000
#define BLOCK 256

__device__ __forceinline__ uint32_t h2_as_u32(__half2 h) {
    return *reinterpret_cast<uint32_t*>(&h);
}
__device__ __forceinline__ __half2 u32_as_h2(uint32_t u) {
    return *reinterpret_cast<__half2*>(&u);
}

// 32B per-face record: slot k (8B): u[2k]=(ck.x,ck.y), u[2k+1]=(ck.z,pad). 6.4MB, L2-resident.
struct alignas(32) FaceRec { uint32_t u[8]; };
__device__ FaceRec g_face_tab[F_MAX];

// 256-bit global load (sm_103a); addr must be 32B-aligned.
__device__ __forceinline__ void ldg256(const void* p, uint32_t* a) {
    asm volatile("ld.global.v8.b32 {%0,%1,%2,%3,%4,%5,%6,%7}, [%8];"
                 : "=r"(a[0]), "=r"(a[1]), "=r"(a[2]), "=r"(a[3]),
                   "=r"(a[4]), "=r"(a[5]), "=r"(a[6]), "=r"(a[7]) : "l"(p));
}

// ---------------------------------------------------------------------------
// Prepro (R10-proven): one thread per FACE-VERTEX (F*3). 1 coalesced idx load
// + 3 scalar vertex gathers + fp16 pack + one 8B store at the padded slot.
// ---------------------------------------------------------------------------
__global__ void __launch_bounds__(BLOCK)
build_face_tab(const int*   __restrict__ faces,
               const float* __restrict__ verts,
               int nfv)
{
    const int i = blockIdx.x * blockDim.x + threadIdx.x;
    if (i >= nfv) return;
    const int v = __ldg(faces + i);
    const float cx = __ldg(verts + (size_t)v * 3 + 0);
    const float cy = __ldg(verts + (size_t)v * 3 + 1);
    const float cz = __ldg(verts + (size_t)v * 3 + 2);
    uint2 h;
    h.x = h2_as_u32(__floats2half2_rn(cx, cy));
    h.y = h2_as_u32(__floats2half2_rn(cz, 0.0f));
    const int face = i / 3;
    const int slot = i - face * 3;
    reinterpret_cast<uint2*>(&g_face_tab[face])[slot] = h;   // padded layout
}

// ---------------------------------------------------------------------------
// Main shader: R10-proven one-shot body, occupancy-pinned to 8 blocks/SM
// (forces regs <= 32 -> 64 warps/SM -> ~16KB of loads in flight per SM).
// ---------------------------------------------------------------------------
__global__ void __launch_bounds__(BLOCK, 8)
unlit_shader_kernel(const int*   __restrict__ pix_to_face,
                    const float* __restrict__ bary,
                    float*       __restrict__ out,
                    int npix)
{
    const int t  = blockIdx.x * blockDim.x + threadIdx.x;
    const int p0 = t * PPT;
    if (p0 >= npix) return;
    const bool full = (p0 + PPT <= npix);

    // 1) Face indices (vectorized int4, coalesced; sample K=0 in .x).
    int f[PPT];
#pragma unroll
    for (int j = 0; j < PPT; ++j) {
        const int p = p0 + j;
        if (full || p < npix) {
            const int4 s = __ldcs(reinterpret_cast<const int4*>(pix_to_face) + p);
            f[j] = s.x;
        } else {
            f[j] = -1;
        }
    }

    // 2) Barycentric weights (conditional: skips ~20% background traffic).
    float4 w[PPT];
#pragma unroll
    for (int j = 0; j < PPT; ++j) {
        const int p = p0 + j;
        w[j] = (f[j] >= 0)
             ? __ldcs(reinterpret_cast<const float4*>(bary + (size_t)p * (KSAMP * 3)))
             : make_float4(0.f, 0.f, 0.f, 0.f);
    }

    // 3) One 256-bit gather per pixel from the L2-resident fp16 table.
    uint32_t g[PPT][8];
#pragma unroll
    for (int j = 0; j < PPT; ++j) {
        const int fi = (f[j] >= 0) ? f[j] : 0;
        ldg256(&g_face_tab[fi], g[j]);
    }

    // 4) Unpack fp16 -> fp32, barycentric weighted sum.
    //    slot k: g[2k]=(ck.x,ck.y), g[2k+1]=(ck.z,pad)
    float o[PPT * 3];
#pragma unroll
    for (int j = 0; j < PPT; ++j) {
        const float2 a0 = __half22float2(u32_as_h2(g[j][0]));
        const float2 a1 = __half22float2(u32_as_h2(g[j][1]));
        const float2 b0 = __half22float2(u32_as_h2(g[j][2]));
        const float2 b1 = __half22float2(u32_as_h2(g[j][3]));
        const float2 c0 = __half22float2(u32_as_h2(g[j][4]));
        const float2 c1 = __half22float2(u32_as_h2(g[j][5]));
        const float wx = w[j].x, wy = w[j].y, wz = w[j].z;
        o[j * 3 + 0] = wx * a0.x + wy * b0.x + wz * c0.x;
        o[j * 3 + 1] = wx * a0.y + wy * b0.y + wz * c0.y;
        o[j * 3 + 2] = wx * a1.x + wy * b1.x + wz * c1.x;
    }

    // 5) Store 12 contiguous floats -> 3x STG.128, streaming.
    float* ob = out + (size_t)p0 * 3;
    if (full) {
        float4* o4 = reinterpret_cast<float4*>(ob);
        __stcs(o4 + 0, make_float4(o[0], o[1],  o[2],  o[3]));
        __stcs(o4 + 1, make_float4(o[4], o[5],  o[6],  o[7]));
        __stcs(o4 + 2, make_float4(o[8], o[9],  o[10], o[11]));
    } else {
#pragma unroll
        for (int j = 0; j < PPT; ++j) {
            const int p = p0 + j;
            if (p < npix) {
                ob[j * 3 + 0] = o[j * 3 + 0];
                ob[j * 3 + 1] = o[j * 3 + 1];
                ob[j * 3 + 2] = o[j * 3 + 2];
            }
        }
    }
}

extern "C" void kernel_launch(void* const* d_in, const int* in_sizes, int n_in,
                              void* d_out, int out_size)
{
    const int*   pix_to_face = (const int*)  d_in[0];
    const float* bary        = (const float*)d_in[1];
    const int*   faces       = (const int*)  d_in[2];
    const float* verts       = (const float*)d_in[3];
    float*       out         = (float*)      d_out;

    int nfv = in_sizes[2];                       // F*3 face-vertices
    if (nfv > F_MAX * 3) nfv = F_MAX * 3;
    const int npix = in_sizes[0] / KSAMP;        // N*H*W

    build_face_tab<<<(nfv + BLOCK - 1) / BLOCK, BLOCK>>>(faces, verts, nfv);

    const int nthreads = (npix + PPT - 1) / PPT;
    const int grid     = (nthreads + BLOCK - 1) / BLOCK;
    unlit_shader_kernel<<<grid, BLOCK>>>(pix_to_face, bary, out, npix);
}